// round 4
// baseline (speedup 1.0000x reference)
#include <cuda_runtime.h>
#include <cstdint>

#define MAX_ROWS 16384
__device__ float  g_rowsum[MAX_ROWS];
__device__ float  g_rowsq[MAX_ROWS];
__device__ float2 g_coef[MAX_ROWS];   // per GLOBAL row: (a, b) for out = a*x + b

// ---- int32/int64 robustness: harness may deliver int64 refs as int32.
__device__ __forceinline__ bool buf_is_i64(const void* p) {
    const int* q = (const int*)p;
    return (q[1] == 0) && (q[3] == 0) && (q[5] == 0);
}
__device__ __forceinline__ long long load_i(const void* p, int i, bool is64) {
    return is64 ? ((const long long*)p)[i] : (long long)((const int*)p)[i];
}

// ---------------- Kernel 1: per-row sum & sumsq, NATURAL order ----------------
// Warp per global row; no indirection. 128-thread blocks for a big grid.
__global__ void __launch_bounds__(128) row_stats_kernel(
    const float* __restrict__ x, int HW4, int NC)
{
    const int r = (blockIdx.x << 2) + (threadIdx.x >> 5);
    if (r >= NC) return;
    const int lane = threadIdx.x & 31;
    const float4* __restrict__ p = (const float4*)(x + (size_t)r * (size_t)(HW4 * 4));

    float a1 = 0.f, a2 = 0.f, b1 = 0.f, b2 = 0.f;
    float c1 = 0.f, c2 = 0.f, d1 = 0.f, d2 = 0.f;
    const int nfull = (HW4 >> 7) << 7;
    for (int j0 = 0; j0 < nfull; j0 += 128) {
        float4 v0 = p[j0 + lane];
        float4 v1 = p[j0 + 32 + lane];
        float4 v2 = p[j0 + 64 + lane];
        float4 v3 = p[j0 + 96 + lane];
        a1 += (v0.x + v0.y) + (v0.z + v0.w);
        a2 += v0.x*v0.x + v0.y*v0.y + v0.z*v0.z + v0.w*v0.w;
        b1 += (v1.x + v1.y) + (v1.z + v1.w);
        b2 += v1.x*v1.x + v1.y*v1.y + v1.z*v1.z + v1.w*v1.w;
        c1 += (v2.x + v2.y) + (v2.z + v2.w);
        c2 += v2.x*v2.x + v2.y*v2.y + v2.z*v2.z + v2.w*v2.w;
        d1 += (v3.x + v3.y) + (v3.z + v3.w);
        d2 += v3.x*v3.x + v3.y*v3.y + v3.z*v3.z + v3.w*v3.w;
    }
    for (int j = nfull + lane; j < HW4; j += 32) {
        float4 v = p[j];
        a1 += (v.x + v.y) + (v.z + v.w);
        a2 += v.x*v.x + v.y*v.y + v.z*v.z + v.w*v.w;
    }
    float s1 = (a1 + b1) + (c1 + d1);
    float s2 = (a2 + b2) + (c2 + d2);
    #pragma unroll
    for (int o = 16; o; o >>= 1) {
        s1 += __shfl_down_sync(0xffffffffu, s1, o);
        s2 += __shfl_down_sync(0xffffffffu, s2, o);
    }
    if (lane == 0) { g_rowsum[r] = s1; g_rowsq[r] = s2; }
}

// ---------------- Kernel 2: group stats -> per-global-row coefficients -------
// Warp per (n, g). Gathers row partials via indexes, scatters (a,b) to the
// global row so kernel 3 is indirection-free.
__global__ void __launch_bounds__(256) coef_kernel(
    const void* __restrict__ indexes,
    const float* __restrict__ weight,
    const float* __restrict__ bias,
    const void* __restrict__ group_sizes,
    int C, int G, int HW, int NG)
{
    const int b = (blockIdx.x << 3) + (threadIdx.x >> 5);
    if (b >= NG) return;
    const int lane = threadIdx.x & 31;
    const int n = b / G;
    const int g = b - n * G;

    const bool gs64 = buf_is_i64(group_sizes);
    int gsz = (lane < G) ? (int)load_i(group_sizes, lane, gs64) : 0;
    int scan = gsz;
    #pragma unroll
    for (int o = 1; o < 32; o <<= 1) {
        int t = __shfl_up_sync(0xffffffffu, scan, o);
        if (lane >= o) scan += t;
    }
    const int cstart = __shfl_sync(0xffffffffu, scan - gsz, g);
    const int glen   = __shfl_sync(0xffffffffu, gsz, g);

    const bool ix64 = buf_is_i64(indexes);
    float s1 = 0.f, s2 = 0.f;
    long long myrow = -1;
    int myc = -1;
    for (int cc = lane; cc < glen; cc += 32) {     // glen <= 32: one iter
        const int i = n * C + cstart + cc;
        const long long r = load_i(indexes, i, ix64);
        s1 += g_rowsum[(int)r];
        s2 += g_rowsq[(int)r];
        myrow = r; myc = cstart + cc;
    }
    #pragma unroll
    for (int o = 16; o; o >>= 1) {
        s1 += __shfl_xor_sync(0xffffffffu, s1, o);
        s2 += __shfl_xor_sync(0xffffffffu, s2, o);
    }
    const float cnt  = (float)glen * (float)HW;
    const float mu   = s1 / cnt;
    const float var  = (s2 - cnt * mu * mu) / (cnt - 1.0f);
    const float ivar = rsqrtf(var + 1e-12f);
    if (myc >= 0) {
        const float a = ivar * weight[myc];
        g_coef[(int)myrow] = make_float2(a, bias[myc] - mu * a);
    }
}

// ---------------- Kernel 3: normalize, NATURAL order, no indirection --------
__global__ void __launch_bounds__(128) normalize_kernel(
    const float* __restrict__ x,
    float* __restrict__ out,
    int HW4, int NC)
{
    const int r = (blockIdx.x << 2) + (threadIdx.x >> 5);
    if (r >= NC) return;
    const int lane = threadIdx.x & 31;
    const float2 ab = g_coef[r];                 // same addr per warp: broadcast
    const float a = ab.x, bsh = ab.y;

    const size_t off = (size_t)r * (size_t)(HW4 * 4);
    const float4* __restrict__ px = (const float4*)(x + off);
    float4*       __restrict__ po = (float4*)(out + off);

    const int nfull = (HW4 >> 7) << 7;
    for (int j0 = 0; j0 < nfull; j0 += 128) {
        float4 v0 = __ldcs(&px[j0 + lane]);
        float4 v1 = __ldcs(&px[j0 + 32 + lane]);
        float4 v2 = __ldcs(&px[j0 + 64 + lane]);
        float4 v3 = __ldcs(&px[j0 + 96 + lane]);
        v0.x = fmaf(v0.x, a, bsh); v0.y = fmaf(v0.y, a, bsh);
        v0.z = fmaf(v0.z, a, bsh); v0.w = fmaf(v0.w, a, bsh);
        v1.x = fmaf(v1.x, a, bsh); v1.y = fmaf(v1.y, a, bsh);
        v1.z = fmaf(v1.z, a, bsh); v1.w = fmaf(v1.w, a, bsh);
        v2.x = fmaf(v2.x, a, bsh); v2.y = fmaf(v2.y, a, bsh);
        v2.z = fmaf(v2.z, a, bsh); v2.w = fmaf(v2.w, a, bsh);
        v3.x = fmaf(v3.x, a, bsh); v3.y = fmaf(v3.y, a, bsh);
        v3.z = fmaf(v3.z, a, bsh); v3.w = fmaf(v3.w, a, bsh);
        __stcs(&po[j0 + lane], v0);
        __stcs(&po[j0 + 32 + lane], v1);
        __stcs(&po[j0 + 64 + lane], v2);
        __stcs(&po[j0 + 96 + lane], v3);
    }
    for (int j = nfull + lane; j < HW4; j += 32) {
        float4 v = __ldcs(&px[j]);
        v.x = fmaf(v.x, a, bsh); v.y = fmaf(v.y, a, bsh);
        v.z = fmaf(v.z, a, bsh); v.w = fmaf(v.w, a, bsh);
        __stcs(&po[j], v);
    }
}

extern "C" void kernel_launch(void* const* d_in, const int* in_sizes, int n_in,
                              void* d_out, int out_size)
{
    const float* x       = (const float*)d_in[0];
    const float* weight  = (const float*)d_in[1];
    const float* bias    = (const float*)d_in[2];
    const void*  gsizes  = d_in[3];
    const void*  indexes = d_in[4];
    float* out = (float*)d_out;

    const int C   = in_sizes[1];
    const int G   = in_sizes[3];
    const int NC  = in_sizes[4];
    const int HW  = in_sizes[0] / NC;
    const int HW4 = HW / 4;
    const int N   = NC / C;
    const int NG  = N * G;

    row_stats_kernel<<<(NC + 3) / 4, 128>>>(x, HW4, NC);
    coef_kernel<<<(NG + 7) / 8, 256>>>(indexes, weight, bias, gsizes, C, G, HW, NG);
    normalize_kernel<<<(NC + 3) / 4, 128>>>(x, out, HW4, NC);
}

// round 6
// speedup vs baseline: 1.1274x; 1.1274x over previous
#include <cuda_runtime.h>
#include <cstdint>

#define MAX_ROWS 16384
__device__ float  g_rowsum[MAX_ROWS];
__device__ float  g_rowsq[MAX_ROWS];
__device__ float2 g_coef[MAX_ROWS];   // per GLOBAL row: (a, b) for out = a*x + b

// ---- int32/int64 robustness: harness may deliver int64 refs as int32.
__device__ __forceinline__ bool buf_is_i64(const void* p) {
    const int* q = (const int*)p;
    return (q[1] == 0) && (q[3] == 0) && (q[5] == 0);
}
__device__ __forceinline__ long long load_i(const void* p, int i, bool is64) {
    return is64 ? ((const long long*)p)[i] : (long long)((const int*)p)[i];
}

// ---------------- Kernel 1: per-row sum & sumsq, NATURAL order ----------------
// Warp per global row. 8 independent float4 loads in flight per lane.
__global__ void __launch_bounds__(128) row_stats_kernel(
    const float* __restrict__ x, int HW4, int NC)
{
    const int r = (blockIdx.x << 2) + (threadIdx.x >> 5);
    if (r >= NC) return;
    const int lane = threadIdx.x & 31;
    const float4* __restrict__ p = (const float4*)(x + (size_t)r * (size_t)(HW4 * 4));

    float s1a = 0.f, s2a = 0.f, s1b = 0.f, s2b = 0.f;
    const int nfull = HW4 & ~255;                // chunks of 256 float4
    for (int j0 = 0; j0 < nfull; j0 += 256) {
        float4 v[8];
        #pragma unroll
        for (int k = 0; k < 8; ++k) v[k] = p[j0 + (k << 5) + lane];
        #pragma unroll
        for (int k = 0; k < 8; k += 2) {
            s1a += (v[k].x + v[k].y) + (v[k].z + v[k].w);
            s2a += v[k].x*v[k].x + v[k].y*v[k].y + v[k].z*v[k].z + v[k].w*v[k].w;
            s1b += (v[k+1].x + v[k+1].y) + (v[k+1].z + v[k+1].w);
            s2b += v[k+1].x*v[k+1].x + v[k+1].y*v[k+1].y
                 + v[k+1].z*v[k+1].z + v[k+1].w*v[k+1].w;
        }
    }
    for (int j = nfull + lane; j < HW4; j += 32) {
        float4 v = p[j];
        s1a += (v.x + v.y) + (v.z + v.w);
        s2a += v.x*v.x + v.y*v.y + v.z*v.z + v.w*v.w;
    }
    float s1 = s1a + s1b, s2 = s2a + s2b;
    #pragma unroll
    for (int o = 16; o; o >>= 1) {
        s1 += __shfl_down_sync(0xffffffffu, s1, o);
        s2 += __shfl_down_sync(0xffffffffu, s2, o);
    }
    if (lane == 0) { g_rowsum[r] = s1; g_rowsq[r] = s2; }
}

// ---------------- Kernel 2: group stats -> per-global-row coefficients -------
__global__ void __launch_bounds__(256) coef_kernel(
    const void* __restrict__ indexes,
    const float* __restrict__ weight,
    const float* __restrict__ bias,
    const void* __restrict__ group_sizes,
    int C, int G, int HW, int NG)
{
    const int b = (blockIdx.x << 3) + (threadIdx.x >> 5);
    if (b >= NG) return;
    const int lane = threadIdx.x & 31;
    const int n = b / G;
    const int g = b - n * G;

    const bool gs64 = buf_is_i64(group_sizes);
    int gsz = (lane < G) ? (int)load_i(group_sizes, lane, gs64) : 0;
    int scan = gsz;
    #pragma unroll
    for (int o = 1; o < 32; o <<= 1) {
        int t = __shfl_up_sync(0xffffffffu, scan, o);
        if (lane >= o) scan += t;
    }
    const int cstart = __shfl_sync(0xffffffffu, scan - gsz, g);
    const int glen   = __shfl_sync(0xffffffffu, gsz, g);

    const bool ix64 = buf_is_i64(indexes);
    float s1 = 0.f, s2 = 0.f;
    long long myrow = -1;
    int myc = -1;
    for (int cc = lane; cc < glen; cc += 32) {     // glen <= 32: one iter
        const int i = n * C + cstart + cc;
        const long long r = load_i(indexes, i, ix64);
        s1 += g_rowsum[(int)r];
        s2 += g_rowsq[(int)r];
        myrow = r; myc = cstart + cc;
    }
    #pragma unroll
    for (int o = 16; o; o >>= 1) {
        s1 += __shfl_xor_sync(0xffffffffu, s1, o);
        s2 += __shfl_xor_sync(0xffffffffu, s2, o);
    }
    const float cnt  = (float)glen * (float)HW;
    const float mu   = s1 / cnt;
    const float var  = (s2 - cnt * mu * mu) / (cnt - 1.0f);
    const float ivar = rsqrtf(var + 1e-12f);
    if (myc >= 0) {
        const float a = ivar * weight[myc];
        g_coef[(int)myrow] = make_float2(a, bias[myc] - mu * a);
    }
}

// ---------------- Kernel 3: normalize, NATURAL order, no indirection --------
__global__ void __launch_bounds__(128) normalize_kernel(
    const float* __restrict__ x,
    float* __restrict__ out,
    int HW4, int NC)
{
    const int r = (blockIdx.x << 2) + (threadIdx.x >> 5);
    if (r >= NC) return;
    const int lane = threadIdx.x & 31;
    const float2 ab = g_coef[r];                 // same addr per warp: broadcast
    const float a = ab.x, bsh = ab.y;

    const size_t off = (size_t)r * (size_t)(HW4 * 4);
    const float4* __restrict__ px = (const float4*)(x + off);
    float4*       __restrict__ po = (float4*)(out + off);

    const int nfull = HW4 & ~255;
    for (int j0 = 0; j0 < nfull; j0 += 256) {
        float4 v[8];
        #pragma unroll
        for (int k = 0; k < 8; ++k) v[k] = __ldcs(&px[j0 + (k << 5) + lane]);
        #pragma unroll
        for (int k = 0; k < 8; ++k) {
            v[k].x = fmaf(v[k].x, a, bsh);
            v[k].y = fmaf(v[k].y, a, bsh);
            v[k].z = fmaf(v[k].z, a, bsh);
            v[k].w = fmaf(v[k].w, a, bsh);
        }
        #pragma unroll
        for (int k = 0; k < 8; ++k) __stcs(&po[j0 + (k << 5) + lane], v[k]);
    }
    for (int j = nfull + lane; j < HW4; j += 32) {
        float4 v = __ldcs(&px[j]);
        v.x = fmaf(v.x, a, bsh); v.y = fmaf(v.y, a, bsh);
        v.z = fmaf(v.z, a, bsh); v.w = fmaf(v.w, a, bsh);
        __stcs(&po[j], v);
    }
}

extern "C" void kernel_launch(void* const* d_in, const int* in_sizes, int n_in,
                              void* d_out, int out_size)
{
    const float* x       = (const float*)d_in[0];
    const float* weight  = (const float*)d_in[1];
    const float* bias    = (const float*)d_in[2];
    const void*  gsizes  = d_in[3];
    const void*  indexes = d_in[4];
    float* out = (float*)d_out;

    const int C   = in_sizes[1];
    const int G   = in_sizes[3];
    const int NC  = in_sizes[4];
    const int HW  = in_sizes[0] / NC;
    const int HW4 = HW / 4;
    const int N   = NC / C;
    const int NG  = N * G;

    row_stats_kernel<<<(NC + 3) / 4, 128>>>(x, HW4, NC);
    coef_kernel<<<(NG + 7) / 8, 256>>>(indexes, weight, bias, gsizes, C, G, HW, NG);
    normalize_kernel<<<(NC + 3) / 4, 128>>>(x, out, HW4, NC);
}

// round 7
// speedup vs baseline: 1.1281x; 1.0006x over previous
#include <cuda_runtime.h>
#include <cstdint>

#define MAX_ROWS 16384
__device__ float  g_rowsum[MAX_ROWS];
__device__ float  g_rowsq[MAX_ROWS];
__device__ float2 g_coef[MAX_ROWS];   // per GLOBAL row: (a, b) for out = a*x + b

// ---- int32/int64 robustness: harness may deliver int64 refs as int32.
__device__ __forceinline__ bool buf_is_i64(const void* p) {
    const int* q = (const int*)p;
    return (q[1] == 0) && (q[3] == 0) && (q[5] == 0);
}
__device__ __forceinline__ long long load_i(const void* p, int i, bool is64) {
    return is64 ? ((const long long*)p)[i] : (long long)((const int*)p)[i];
}

// ---------------- Kernel 1: per-row sum & sumsq, NATURAL order ----------------
// Warp per global row. 8 independent float4 loads in flight per lane.
__global__ void __launch_bounds__(128) row_stats_kernel(
    const float* __restrict__ x, int HW4, int NC)
{
    const int r = (blockIdx.x << 2) + (threadIdx.x >> 5);
    if (r >= NC) return;
    const int lane = threadIdx.x & 31;
    const float4* __restrict__ p = (const float4*)(x + (size_t)r * (size_t)(HW4 * 4));

    float s1a = 0.f, s2a = 0.f, s1b = 0.f, s2b = 0.f;
    const int nfull = HW4 & ~255;                // chunks of 256 float4
    for (int j0 = 0; j0 < nfull; j0 += 256) {
        float4 v[8];
        #pragma unroll
        for (int k = 0; k < 8; ++k) v[k] = p[j0 + (k << 5) + lane];
        #pragma unroll
        for (int k = 0; k < 8; k += 2) {
            s1a += (v[k].x + v[k].y) + (v[k].z + v[k].w);
            s2a += v[k].x*v[k].x + v[k].y*v[k].y + v[k].z*v[k].z + v[k].w*v[k].w;
            s1b += (v[k+1].x + v[k+1].y) + (v[k+1].z + v[k+1].w);
            s2b += v[k+1].x*v[k+1].x + v[k+1].y*v[k+1].y
                 + v[k+1].z*v[k+1].z + v[k+1].w*v[k+1].w;
        }
    }
    for (int j = nfull + lane; j < HW4; j += 32) {
        float4 v = p[j];
        s1a += (v.x + v.y) + (v.z + v.w);
        s2a += v.x*v.x + v.y*v.y + v.z*v.z + v.w*v.w;
    }
    float s1 = s1a + s1b, s2 = s2a + s2b;
    #pragma unroll
    for (int o = 16; o; o >>= 1) {
        s1 += __shfl_down_sync(0xffffffffu, s1, o);
        s2 += __shfl_down_sync(0xffffffffu, s2, o);
    }
    if (lane == 0) { g_rowsum[r] = s1; g_rowsq[r] = s2; }
}

// ---------------- Kernel 2: group stats -> per-global-row coefficients -------
__global__ void __launch_bounds__(256) coef_kernel(
    const void* __restrict__ indexes,
    const float* __restrict__ weight,
    const float* __restrict__ bias,
    const void* __restrict__ group_sizes,
    int C, int G, int HW, int NG)
{
    const int b = (blockIdx.x << 3) + (threadIdx.x >> 5);
    if (b >= NG) return;
    const int lane = threadIdx.x & 31;
    const int n = b / G;
    const int g = b - n * G;

    const bool gs64 = buf_is_i64(group_sizes);
    int gsz = (lane < G) ? (int)load_i(group_sizes, lane, gs64) : 0;
    int scan = gsz;
    #pragma unroll
    for (int o = 1; o < 32; o <<= 1) {
        int t = __shfl_up_sync(0xffffffffu, scan, o);
        if (lane >= o) scan += t;
    }
    const int cstart = __shfl_sync(0xffffffffu, scan - gsz, g);
    const int glen   = __shfl_sync(0xffffffffu, gsz, g);

    const bool ix64 = buf_is_i64(indexes);
    float s1 = 0.f, s2 = 0.f;
    long long myrow = -1;
    int myc = -1;
    for (int cc = lane; cc < glen; cc += 32) {     // glen <= 32: one iter
        const int i = n * C + cstart + cc;
        const long long r = load_i(indexes, i, ix64);
        s1 += g_rowsum[(int)r];
        s2 += g_rowsq[(int)r];
        myrow = r; myc = cstart + cc;
    }
    #pragma unroll
    for (int o = 16; o; o >>= 1) {
        s1 += __shfl_xor_sync(0xffffffffu, s1, o);
        s2 += __shfl_xor_sync(0xffffffffu, s2, o);
    }
    const float cnt  = (float)glen * (float)HW;
    const float mu   = s1 / cnt;
    const float var  = (s2 - cnt * mu * mu) / (cnt - 1.0f);
    const float ivar = rsqrtf(var + 1e-12f);
    if (myc >= 0) {
        const float a = ivar * weight[myc];
        g_coef[(int)myrow] = make_float2(a, bias[myc] - mu * a);
    }
}

// ---------------- Kernel 3: normalize, REVERSE row order --------------------
// K1 streamed rows 0..NC-1 into L2 (~103MB vs ~126MB capacity): the tail rows
// are still resident (MRU). Reading in reverse order maximizes L2 hits instead
// of chasing the eviction wavefront.
__global__ void __launch_bounds__(128) normalize_kernel(
    const float* __restrict__ x,
    float* __restrict__ out,
    int HW4, int NC)
{
    const int rf = (blockIdx.x << 2) + (threadIdx.x >> 5);
    if (rf >= NC) return;
    const int r = NC - 1 - rf;                   // reverse traversal
    const int lane = threadIdx.x & 31;
    const float2 ab = g_coef[r];                 // same addr per warp: broadcast
    const float a = ab.x, bsh = ab.y;

    const size_t off = (size_t)r * (size_t)(HW4 * 4);
    const float4* __restrict__ px = (const float4*)(x + off);
    float4*       __restrict__ po = (float4*)(out + off);

    const int nfull = HW4 & ~255;
    for (int j0 = 0; j0 < nfull; j0 += 256) {
        float4 v[8];
        #pragma unroll
        for (int k = 0; k < 8; ++k) v[k] = __ldcs(&px[j0 + (k << 5) + lane]);
        #pragma unroll
        for (int k = 0; k < 8; ++k) {
            v[k].x = fmaf(v[k].x, a, bsh);
            v[k].y = fmaf(v[k].y, a, bsh);
            v[k].z = fmaf(v[k].z, a, bsh);
            v[k].w = fmaf(v[k].w, a, bsh);
        }
        #pragma unroll
        for (int k = 0; k < 8; ++k) __stcs(&po[j0 + (k << 5) + lane], v[k]);
    }
    for (int j = nfull + lane; j < HW4; j += 32) {
        float4 v = __ldcs(&px[j]);
        v.x = fmaf(v.x, a, bsh); v.y = fmaf(v.y, a, bsh);
        v.z = fmaf(v.z, a, bsh); v.w = fmaf(v.w, a, bsh);
        __stcs(&po[j], v);
    }
}

extern "C" void kernel_launch(void* const* d_in, const int* in_sizes, int n_in,
                              void* d_out, int out_size)
{
    const float* x       = (const float*)d_in[0];
    const float* weight  = (const float*)d_in[1];
    const float* bias    = (const float*)d_in[2];
    const void*  gsizes  = d_in[3];
    const void*  indexes = d_in[4];
    float* out = (float*)d_out;

    const int C   = in_sizes[1];
    const int G   = in_sizes[3];
    const int NC  = in_sizes[4];
    const int HW  = in_sizes[0] / NC;
    const int HW4 = HW / 4;
    const int N   = NC / C;
    const int NG  = N * G;

    row_stats_kernel<<<(NC + 3) / 4, 128>>>(x, HW4, NC);
    coef_kernel<<<(NG + 7) / 8, 256>>>(indexes, weight, bias, gsizes, C, G, HW, NG);
    normalize_kernel<<<(NC + 3) / 4, 128>>>(x, out, HW4, NC);
}